// round 14
// baseline (speedup 1.0000x reference)
#include <cuda_runtime.h>
#include <cstdint>
#include <cstddef>

// ---------------------------------------------------------------------------
// SSIM loss, fused single kernel — 4-channel sum/difference formulation with
// DUAL-ACCUMULATOR aligned-only horizontal conv (R13 base):
//   a = p+t, b = p-t;  conv(a), conv(b), conv(a^2), conv(b^2) suffice.
//   ACC1 += X[m] * rep(W[2m-1])        (m = 1..5)
//   ACC2 += X[m] * pack(W[2m-2],W[2m]) (m = 0..6, zero-padded ends)
//   h = add2(ACC1, rot32(ACC2))   // (A1.lo+A2.hi, A1.hi+A2.lo), packed
// R14 deltas: rot32+add2 combine (replaces unpack/scalar-add/pack),
//             __launch_bounds__(64,7) -> 14 warps/SM.
// Block: 128 output cols x 64 output rows; 64 threads, 2 cols/thread.
// cp.async double-buffered streaming; 11-slot rolling f32x2 ring (4 ch),
// warp-uniform guarded scatter (proven structure).
// ---------------------------------------------------------------------------

#define IMG_H 512
#define IMG_W 512
#define NBATCH 32
#define THREADS 64
#define TW 128              // output cols per block
#define RH 64               // output rows per block
#define NIN (RH + 10)       // 74 input rows touched
#define RAWW 144            // staged row width in floats ([x0-8, x0+136))
#define NV4 (RAWW / 4)      // 36 float4 per row
#define GROUP 11
#define NGROUPS ((NIN + GROUP - 1) / GROUP)   // 7
#define NBLOCKS ((IMG_W / TW) * (IMG_H / RH) * NBATCH)   // 1024

using ull = unsigned long long;

__device__ double   g_accum = 0.0;
__device__ unsigned g_count = 0;

// ---- packed f32x2 helpers (sm_103a) ----
__device__ __forceinline__ ull pack2(float lo, float hi) {
    ull r; asm("mov.b64 %0, {%1, %2};" : "=l"(r) : "f"(lo), "f"(hi)); return r;
}
__device__ __forceinline__ ull fma2(ull a, ull b, ull c) {
    ull r; asm("fma.rn.f32x2 %0, %1, %2, %3;" : "=l"(r) : "l"(a), "l"(b), "l"(c)); return r;
}
__device__ __forceinline__ ull mul2(ull a, ull b) {
    ull r; asm("mul.rn.f32x2 %0, %1, %2;" : "=l"(r) : "l"(a), "l"(b)); return r;
}
__device__ __forceinline__ ull add2(ull a, ull b) {
    ull r; asm("add.rn.f32x2 %0, %1, %2;" : "=l"(r) : "l"(a), "l"(b)); return r;
}
__device__ __forceinline__ ull rot32(ull v) {           // swap 32-bit halves
    return (v << 32) | (v >> 32);
}
__device__ __forceinline__ float2 unpk2(ull v) {
    float2 f; asm("mov.b64 {%0, %1}, %2;" : "=f"(f.x), "=f"(f.y) : "l"(v)); return f;
}

__device__ __forceinline__ unsigned smem_u32(const void* p) {
    return (unsigned)__cvta_generic_to_shared(p);
}
__device__ __forceinline__ void cp_async16(unsigned saddr, const void* gaddr, int srcsize) {
    asm volatile("cp.async.ca.shared.global [%0], [%1], 16, %2;\n"
                 :: "r"(saddr), "l"(gaddr), "r"(srcsize));
}
__device__ __forceinline__ void cp_commit() { asm volatile("cp.async.commit_group;\n" ::: "memory"); }
__device__ __forceinline__ void cp_wait1()  { asm volatile("cp.async.wait_group 1;\n" ::: "memory"); }
__device__ __forceinline__ void cp_wait0()  { asm volatile("cp.async.wait_group 0;\n" ::: "memory"); }

// Issue cp.async for one 11-row group of both tensors into sbuf.
__device__ __forceinline__ void load_group(float* sbuf,  // [2][GROUP][RAWW]
                                           const float* __restrict__ P,
                                           const float* __restrict__ T,
                                           int g, int x0, int y0) {
    const int total = 2 * GROUP * NV4;  // 792
    for (int idx = threadIdx.x; idx < total; idx += THREADS) {
        int tsel = idx / (GROUP * NV4);
        int rem  = idx % (GROUP * NV4);
        int r    = rem / NV4;
        int cv   = rem % NV4;
        int i    = g * GROUP + r;
        int ir   = y0 - 5 + i;
        int c0   = x0 - 8 + cv * 4;
        bool ok = (i < NIN) && ((unsigned)ir < (unsigned)IMG_H) && ((unsigned)c0 < (unsigned)IMG_W);
        const float* src = tsel ? T : P;
        const float* gp  = ok ? (src + (size_t)ir * IMG_W + c0) : src;
        unsigned sa = smem_u32(sbuf + (tsel * GROUP + r) * RAWW + cv * 4);
        cp_async16(sa, gp, ok ? 16 : 0);
    }
}

__global__ void __launch_bounds__(THREADS, 7)
ssim_main(const float* __restrict__ pred, const float* __restrict__ targ,
          float* __restrict__ out) {
    __shared__ __align__(16) float sraw[2][2][GROUP][RAWW];   // 24.75 KB
    __shared__ float sred[THREADS / 32];
    __shared__ bool amLast;

    const int x0 = blockIdx.x * TW;
    const int y0 = blockIdx.y * RH;
    const int b  = blockIdx.z;
    const float* P = pred + (size_t)b * (IMG_H * IMG_W);
    const float* T = targ + (size_t)b * (IMG_H * IMG_W);
    const int tid  = threadIdx.x;
    const int tid2 = 2 * tid;

    // 1D Gaussian weights (normalized) as compile-time literals.
    const float Wc[11] = {
        1.4867195e-06f, 1.3383023e-04f, 4.4318484e-03f, 5.3990967e-02f,
        2.4197073e-01f, 3.9894228e-01f, 2.4197073e-01f, 5.3990967e-02f,
        4.4318484e-03f, 1.3383023e-04f, 1.4867195e-06f };
    const float C1f = 1e-4f;   // 0.01^2
    const float C2f = 9e-4f;   // 0.03^2

    // Packed scatter weights (replicated), loop-invariant.
    ull W2[11];
    #pragma unroll
    for (int k = 0; k < 11; ++k) W2[k] = pack2(Wc[k], Wc[k]);
    const ull ONE2 = pack2(1.0f, 1.0f);
    const ull NEG2 = pack2(-1.0f, -1.0f);

    // Dual-accumulator hconv weights:
    // RW[m] = rep(W[2m-1]), m=1..5 ; PW[m] = (W[2m-2], W[2m]), m=0..6 (0-padded)
    ull RW[6], PW[7];
    #pragma unroll
    for (int m = 1; m <= 5; ++m) RW[m] = pack2(Wc[2 * m - 1], Wc[2 * m - 1]);
    PW[0] = pack2(0.0f, Wc[0]);
    #pragma unroll
    for (int m = 1; m <= 5; ++m) PW[m] = pack2(Wc[2 * m - 2], Wc[2 * m]);
    PW[6] = pack2(Wc[10], 0.0f);

    // Rolling vertical accumulators: 4 channels (a, b, a^2, b^2) x 11 slots.
    ull acc[4][GROUP];
    #pragma unroll
    for (int c = 0; c < 4; ++c)
        #pragma unroll
        for (int s = 0; s < GROUP; ++s) acc[c][s] = 0ull;

    float tsum = 0.f;

    // Prologue: prefetch group 0
    load_group(&sraw[0][0][0][0], P, T, 0, x0, y0);
    cp_commit();

    #pragma unroll 1
    for (int g = 0; g < NGROUPS; ++g) {
        if (g + 1 < NGROUPS) {
            load_group(&sraw[(g + 1) & 1][0][0][0], P, T, g + 1, x0, y0);
            cp_commit();
            cp_wait1();     // group g complete, group g+1 may be in flight
        } else {
            cp_wait0();
        }
        __syncthreads();

        const float* basep = &sraw[g & 1][0][0][0];
        const float* baset = &sraw[g & 1][1][0][0];

        #pragma unroll
        for (int j = 0; j < GROUP; ++j) {
            const int i = g * GROUP + j;
            if (i < NIN) {
                // ---- load aligned p/t pairs, form a = p+t, b = p-t ----
                ull Aa[7], Ab[7];
                #pragma unroll
                for (int m = 0; m < 7; ++m) {
                    ull Apm = *(const ull*)(basep + j * RAWW + tid2 + 2 + 2 * m);
                    ull Atm = *(const ull*)(baset + j * RAWW + tid2 + 2 + 2 * m);
                    Aa[m] = fma2(Atm, ONE2, Apm);   // p + t
                    Ab[m] = fma2(Atm, NEG2, Apm);   // p - t
                }

                // ---- dual-accumulator hconv over 4 channels ----
                ull A1a, A1b, A1sa, A1sb;   // ACC1 (m = 1..5)
                ull A2a, A2b, A2sa, A2sb;   // ACC2 (m = 0..6)
                {   // m = 0: ACC2 init
                    ull sa = mul2(Aa[0], Aa[0]);
                    ull sb = mul2(Ab[0], Ab[0]);
                    A2a  = mul2(Aa[0], PW[0]);
                    A2b  = mul2(Ab[0], PW[0]);
                    A2sa = mul2(sa,    PW[0]);
                    A2sb = mul2(sb,    PW[0]);
                }
                #pragma unroll
                for (int m = 1; m <= 5; ++m) {
                    ull sa = mul2(Aa[m], Aa[m]);
                    ull sb = mul2(Ab[m], Ab[m]);
                    if (m == 1) {
                        A1a  = mul2(Aa[m], RW[m]);
                        A1b  = mul2(Ab[m], RW[m]);
                        A1sa = mul2(sa,    RW[m]);
                        A1sb = mul2(sb,    RW[m]);
                    } else {
                        A1a  = fma2(Aa[m], RW[m], A1a);
                        A1b  = fma2(Ab[m], RW[m], A1b);
                        A1sa = fma2(sa,    RW[m], A1sa);
                        A1sb = fma2(sb,    RW[m], A1sb);
                    }
                    A2a  = fma2(Aa[m], PW[m], A2a);
                    A2b  = fma2(Ab[m], PW[m], A2b);
                    A2sa = fma2(sa,    PW[m], A2sa);
                    A2sb = fma2(sb,    PW[m], A2sb);
                }
                {   // m = 6: ACC2 tail
                    ull sa = mul2(Aa[6], Aa[6]);
                    ull sb = mul2(Ab[6], Ab[6]);
                    A2a  = fma2(Aa[6], PW[6], A2a);
                    A2b  = fma2(Ab[6], PW[6], A2b);
                    A2sa = fma2(sa,    PW[6], A2sa);
                    A2sb = fma2(sb,    PW[6], A2sb);
                }
                // combine: h = ACC1 + rot32(ACC2) -> (A1.lo+A2.hi, A1.hi+A2.lo)
                ull ha  = add2(A1a,  rot32(A2a));
                ull hb  = add2(A1b,  rot32(A2b));
                ull ha2 = add2(A1sa, rot32(A2sa));
                ull hb2 = add2(A1sb, rot32(A2sb));
                ull h[4] = { ha, hb, ha2, hb2 };

                // ---- vertical scatter into rolling ring (warp-uniform guards) ----
                #pragma unroll
                for (int k = 0; k < 11; ++k) {
                    const int s = (j - k + 11) % 11;     // compile-time
                    bool on = (i >= k) && (i - k < RH);
                    if (on) {
                        #pragma unroll
                        for (int ch = 0; ch < 4; ++ch) {
                            if (k == 0) acc[ch][s] = mul2(h[ch], W2[0]);   // fresh slot
                            else        acc[ch][s] = fma2(h[ch], W2[k], acc[ch][s]);
                        }
                    }
                }

                // ---- finalize output row oy = i - 10 ----
                if (i >= 10) {
                    const int f = (j + 1) % 11;          // compile-time
                    float2 mav = unpk2(acc[0][f]);   // mu_a = mu1+mu2
                    float2 mbv = unpk2(acc[1][f]);   // mu_b = mu1-mu2
                    float2 eav = unpk2(acc[2][f]);   // E[(p+t)^2]
                    float2 ebv = unpk2(acc[3][f]);   // E[(p-t)^2]
                    float n[2], d[2];
                    #pragma unroll
                    for (int v = 0; v < 2; ++v) {
                        float ma = v ? mav.y : mav.x;
                        float mb = v ? mbv.y : mbv.x;
                        float ea = v ? eav.y : eav.x;
                        float eb = v ? ebv.y : ebv.x;
                        float m2a = ma * ma;
                        float m2b = mb * mb;
                        float mp = m2a + m2b;   // 2(mu1^2 + mu2^2)
                        float mm = m2a - m2b;   // 4 mu1 mu2
                        float ep = ea + eb;     // 2(E[p^2] + E[t^2])
                        float em = ea - eb;     // 4 E[pt]
                        float num1 = fmaf(0.5f, mm, C1f);
                        float num2 = fmaf(0.5f, em - mm, C2f);
                        float den1 = fmaf(0.5f, mp, C1f);
                        float den2 = fmaf(0.5f, ep - mp, C2f);
                        n[v] = num1 * num2;
                        d[v] = den1 * den2;
                    }
                    // n0/d0 + n1/d1 = (n0*d1 + n1*d0) * rcp(d0*d1); d > C1*C2 > 0
                    float num = n[0] * d[1] + n[1] * d[0];
                    float rden;
                    asm("rcp.approx.f32 %0, %1;" : "=f"(rden) : "f"(d[0] * d[1]));
                    tsum = fmaf(num, rden, tsum);
                }
            }
        }
        __syncthreads();   // protect buffer (g&1) before next prefetch reuses it
    }

    // ---- block reduction -> global double accumulator ----
    float s = tsum;
    #pragma unroll
    for (int off = 16; off; off >>= 1)
        s += __shfl_xor_sync(0xffffffffu, s, off);
    if ((tid & 31) == 0) sred[tid >> 5] = s;
    __syncthreads();
    if (tid == 0) {
        atomicAdd(&g_accum, (double)(sred[0] + sred[1]));
        __threadfence();
        unsigned prev = atomicAdd(&g_count, 1u);
        amLast = (prev == (unsigned)(NBLOCKS - 1));
    }
    __syncthreads();

    // ---- last block finalizes and resets state for the next graph replay ----
    if (amLast && tid == 0) {
        double total = atomicAdd(&g_accum, 0.0);   // coherent read
        out[0] = (float)(1.0 - total * (1.0 / (double)(NBATCH * IMG_H * IMG_W)));
        g_accum = 0.0;
        g_count = 0u;
    }
}

extern "C" void kernel_launch(void* const* d_in, const int* in_sizes, int n_in,
                              void* d_out, int out_size) {
    const float* pred = (const float*)d_in[0];
    const float* targ = (const float*)d_in[1];
    // d_in[2] (window) is a fixed Gaussian; weights are baked as immediates.
    (void)in_sizes; (void)n_in; (void)out_size;

    dim3 grid(IMG_W / TW, IMG_H / RH, NBATCH);   // 4 x 8 x 32 = 1024 blocks
    ssim_main<<<grid, THREADS>>>(pred, targ, (float*)d_out);
}

// round 15
// speedup vs baseline: 1.0212x; 1.0212x over previous
#include <cuda_runtime.h>
#include <cstdint>
#include <cstddef>

// ---------------------------------------------------------------------------
// SSIM loss, fused single kernel — 4-channel sum/difference formulation with
// DUAL-ACCUMULATOR aligned-only horizontal conv (R13 base, 6 blocks/SM):
//   a = p+t, b = p-t;  conv(a), conv(b), conv(a^2), conv(b^2) suffice.
//   ACC1 += X[m] * rep(W[2m-1])        (m = 1..5)
//   ACC2 += X[m] * pack(W[2m-2],W[2m]) (m = 0..6, zero-padded ends)
//   h = add2(ACC1, rot32(ACC2))   // (A1.lo+A2.hi, A1.hi+A2.lo), packed
// R15 delta vs R13: ONLY the rot32+add2 combine (launch bounds stay at 6 —
// R14 showed capping regs below the natural 141 triggers rematerialization).
// Block: 128 output cols x 64 output rows; 64 threads, 2 cols/thread.
// cp.async double-buffered streaming; 11-slot rolling f32x2 ring (4 ch),
// warp-uniform guarded scatter (proven structure).
// ---------------------------------------------------------------------------

#define IMG_H 512
#define IMG_W 512
#define NBATCH 32
#define THREADS 64
#define TW 128              // output cols per block
#define RH 64               // output rows per block
#define NIN (RH + 10)       // 74 input rows touched
#define RAWW 144            // staged row width in floats ([x0-8, x0+136))
#define NV4 (RAWW / 4)      // 36 float4 per row
#define GROUP 11
#define NGROUPS ((NIN + GROUP - 1) / GROUP)   // 7
#define NBLOCKS ((IMG_W / TW) * (IMG_H / RH) * NBATCH)   // 1024

using ull = unsigned long long;

__device__ double   g_accum = 0.0;
__device__ unsigned g_count = 0;

// ---- packed f32x2 helpers (sm_103a) ----
__device__ __forceinline__ ull pack2(float lo, float hi) {
    ull r; asm("mov.b64 %0, {%1, %2};" : "=l"(r) : "f"(lo), "f"(hi)); return r;
}
__device__ __forceinline__ ull fma2(ull a, ull b, ull c) {
    ull r; asm("fma.rn.f32x2 %0, %1, %2, %3;" : "=l"(r) : "l"(a), "l"(b), "l"(c)); return r;
}
__device__ __forceinline__ ull mul2(ull a, ull b) {
    ull r; asm("mul.rn.f32x2 %0, %1, %2;" : "=l"(r) : "l"(a), "l"(b)); return r;
}
__device__ __forceinline__ ull add2(ull a, ull b) {
    ull r; asm("add.rn.f32x2 %0, %1, %2;" : "=l"(r) : "l"(a), "l"(b)); return r;
}
__device__ __forceinline__ ull rot32(ull v) {           // swap 32-bit halves
    return (v << 32) | (v >> 32);
}
__device__ __forceinline__ float2 unpk2(ull v) {
    float2 f; asm("mov.b64 {%0, %1}, %2;" : "=f"(f.x), "=f"(f.y) : "l"(v)); return f;
}

__device__ __forceinline__ unsigned smem_u32(const void* p) {
    return (unsigned)__cvta_generic_to_shared(p);
}
__device__ __forceinline__ void cp_async16(unsigned saddr, const void* gaddr, int srcsize) {
    asm volatile("cp.async.ca.shared.global [%0], [%1], 16, %2;\n"
                 :: "r"(saddr), "l"(gaddr), "r"(srcsize));
}
__device__ __forceinline__ void cp_commit() { asm volatile("cp.async.commit_group;\n" ::: "memory"); }
__device__ __forceinline__ void cp_wait1()  { asm volatile("cp.async.wait_group 1;\n" ::: "memory"); }
__device__ __forceinline__ void cp_wait0()  { asm volatile("cp.async.wait_group 0;\n" ::: "memory"); }

// Issue cp.async for one 11-row group of both tensors into sbuf.
__device__ __forceinline__ void load_group(float* sbuf,  // [2][GROUP][RAWW]
                                           const float* __restrict__ P,
                                           const float* __restrict__ T,
                                           int g, int x0, int y0) {
    const int total = 2 * GROUP * NV4;  // 792
    for (int idx = threadIdx.x; idx < total; idx += THREADS) {
        int tsel = idx / (GROUP * NV4);
        int rem  = idx % (GROUP * NV4);
        int r    = rem / NV4;
        int cv   = rem % NV4;
        int i    = g * GROUP + r;
        int ir   = y0 - 5 + i;
        int c0   = x0 - 8 + cv * 4;
        bool ok = (i < NIN) && ((unsigned)ir < (unsigned)IMG_H) && ((unsigned)c0 < (unsigned)IMG_W);
        const float* src = tsel ? T : P;
        const float* gp  = ok ? (src + (size_t)ir * IMG_W + c0) : src;
        unsigned sa = smem_u32(sbuf + (tsel * GROUP + r) * RAWW + cv * 4);
        cp_async16(sa, gp, ok ? 16 : 0);
    }
}

__global__ void __launch_bounds__(THREADS, 6)
ssim_main(const float* __restrict__ pred, const float* __restrict__ targ,
          float* __restrict__ out) {
    __shared__ __align__(16) float sraw[2][2][GROUP][RAWW];   // 24.75 KB
    __shared__ float sred[THREADS / 32];
    __shared__ bool amLast;

    const int x0 = blockIdx.x * TW;
    const int y0 = blockIdx.y * RH;
    const int b  = blockIdx.z;
    const float* P = pred + (size_t)b * (IMG_H * IMG_W);
    const float* T = targ + (size_t)b * (IMG_H * IMG_W);
    const int tid  = threadIdx.x;
    const int tid2 = 2 * tid;

    // 1D Gaussian weights (normalized) as compile-time literals.
    const float Wc[11] = {
        1.4867195e-06f, 1.3383023e-04f, 4.4318484e-03f, 5.3990967e-02f,
        2.4197073e-01f, 3.9894228e-01f, 2.4197073e-01f, 5.3990967e-02f,
        4.4318484e-03f, 1.3383023e-04f, 1.4867195e-06f };
    const float C1f = 1e-4f;   // 0.01^2
    const float C2f = 9e-4f;   // 0.03^2

    // Packed scatter weights (replicated), loop-invariant.
    ull W2[11];
    #pragma unroll
    for (int k = 0; k < 11; ++k) W2[k] = pack2(Wc[k], Wc[k]);
    const ull ONE2 = pack2(1.0f, 1.0f);
    const ull NEG2 = pack2(-1.0f, -1.0f);

    // Dual-accumulator hconv weights:
    // RW[m] = rep(W[2m-1]), m=1..5 ; PW[m] = (W[2m-2], W[2m]), m=0..6 (0-padded)
    ull RW[6], PW[7];
    #pragma unroll
    for (int m = 1; m <= 5; ++m) RW[m] = pack2(Wc[2 * m - 1], Wc[2 * m - 1]);
    PW[0] = pack2(0.0f, Wc[0]);
    #pragma unroll
    for (int m = 1; m <= 5; ++m) PW[m] = pack2(Wc[2 * m - 2], Wc[2 * m]);
    PW[6] = pack2(Wc[10], 0.0f);

    // Rolling vertical accumulators: 4 channels (a, b, a^2, b^2) x 11 slots.
    ull acc[4][GROUP];
    #pragma unroll
    for (int c = 0; c < 4; ++c)
        #pragma unroll
        for (int s = 0; s < GROUP; ++s) acc[c][s] = 0ull;

    float tsum = 0.f;

    // Prologue: prefetch group 0
    load_group(&sraw[0][0][0][0], P, T, 0, x0, y0);
    cp_commit();

    #pragma unroll 1
    for (int g = 0; g < NGROUPS; ++g) {
        if (g + 1 < NGROUPS) {
            load_group(&sraw[(g + 1) & 1][0][0][0], P, T, g + 1, x0, y0);
            cp_commit();
            cp_wait1();     // group g complete, group g+1 may be in flight
        } else {
            cp_wait0();
        }
        __syncthreads();

        const float* basep = &sraw[g & 1][0][0][0];
        const float* baset = &sraw[g & 1][1][0][0];

        #pragma unroll
        for (int j = 0; j < GROUP; ++j) {
            const int i = g * GROUP + j;
            if (i < NIN) {
                // ---- load aligned p/t pairs, form a = p+t, b = p-t ----
                ull Aa[7], Ab[7];
                #pragma unroll
                for (int m = 0; m < 7; ++m) {
                    ull Apm = *(const ull*)(basep + j * RAWW + tid2 + 2 + 2 * m);
                    ull Atm = *(const ull*)(baset + j * RAWW + tid2 + 2 + 2 * m);
                    Aa[m] = fma2(Atm, ONE2, Apm);   // p + t
                    Ab[m] = fma2(Atm, NEG2, Apm);   // p - t
                }

                // ---- dual-accumulator hconv over 4 channels ----
                // squares computed per aligned pair, consumed immediately.
                ull A1a, A1b, A1sa, A1sb;   // ACC1 (m = 1..5)
                ull A2a, A2b, A2sa, A2sb;   // ACC2 (m = 0..6)
                {   // m = 0: ACC2 init
                    ull sa = mul2(Aa[0], Aa[0]);
                    ull sb = mul2(Ab[0], Ab[0]);
                    A2a  = mul2(Aa[0], PW[0]);
                    A2b  = mul2(Ab[0], PW[0]);
                    A2sa = mul2(sa,    PW[0]);
                    A2sb = mul2(sb,    PW[0]);
                }
                #pragma unroll
                for (int m = 1; m <= 5; ++m) {
                    ull sa = mul2(Aa[m], Aa[m]);
                    ull sb = mul2(Ab[m], Ab[m]);
                    if (m == 1) {
                        A1a  = mul2(Aa[m], RW[m]);
                        A1b  = mul2(Ab[m], RW[m]);
                        A1sa = mul2(sa,    RW[m]);
                        A1sb = mul2(sb,    RW[m]);
                    } else {
                        A1a  = fma2(Aa[m], RW[m], A1a);
                        A1b  = fma2(Ab[m], RW[m], A1b);
                        A1sa = fma2(sa,    RW[m], A1sa);
                        A1sb = fma2(sb,    RW[m], A1sb);
                    }
                    A2a  = fma2(Aa[m], PW[m], A2a);
                    A2b  = fma2(Ab[m], PW[m], A2b);
                    A2sa = fma2(sa,    PW[m], A2sa);
                    A2sb = fma2(sb,    PW[m], A2sb);
                }
                {   // m = 6: ACC2 tail
                    ull sa = mul2(Aa[6], Aa[6]);
                    ull sb = mul2(Ab[6], Ab[6]);
                    A2a  = fma2(Aa[6], PW[6], A2a);
                    A2b  = fma2(Ab[6], PW[6], A2b);
                    A2sa = fma2(sa,    PW[6], A2sa);
                    A2sb = fma2(sb,    PW[6], A2sb);
                }
                // combine: h = ACC1 + rot32(ACC2) -> (A1.lo+A2.hi, A1.hi+A2.lo)
                ull ha  = add2(A1a,  rot32(A2a));
                ull hb  = add2(A1b,  rot32(A2b));
                ull ha2 = add2(A1sa, rot32(A2sa));
                ull hb2 = add2(A1sb, rot32(A2sb));
                ull h[4] = { ha, hb, ha2, hb2 };

                // ---- vertical scatter into rolling ring (warp-uniform guards) ----
                #pragma unroll
                for (int k = 0; k < 11; ++k) {
                    const int s = (j - k + 11) % 11;     // compile-time
                    bool on = (i >= k) && (i - k < RH);
                    if (on) {
                        #pragma unroll
                        for (int ch = 0; ch < 4; ++ch) {
                            if (k == 0) acc[ch][s] = mul2(h[ch], W2[0]);   // fresh slot
                            else        acc[ch][s] = fma2(h[ch], W2[k], acc[ch][s]);
                        }
                    }
                }

                // ---- finalize output row oy = i - 10 ----
                if (i >= 10) {
                    const int f = (j + 1) % 11;          // compile-time
                    float2 mav = unpk2(acc[0][f]);   // mu_a = mu1+mu2
                    float2 mbv = unpk2(acc[1][f]);   // mu_b = mu1-mu2
                    float2 eav = unpk2(acc[2][f]);   // E[(p+t)^2]
                    float2 ebv = unpk2(acc[3][f]);   // E[(p-t)^2]
                    float n[2], d[2];
                    #pragma unroll
                    for (int v = 0; v < 2; ++v) {
                        float ma = v ? mav.y : mav.x;
                        float mb = v ? mbv.y : mbv.x;
                        float ea = v ? eav.y : eav.x;
                        float eb = v ? ebv.y : ebv.x;
                        float m2a = ma * ma;
                        float m2b = mb * mb;
                        float mp = m2a + m2b;   // 2(mu1^2 + mu2^2)
                        float mm = m2a - m2b;   // 4 mu1 mu2
                        float ep = ea + eb;     // 2(E[p^2] + E[t^2])
                        float em = ea - eb;     // 4 E[pt]
                        float num1 = fmaf(0.5f, mm, C1f);
                        float num2 = fmaf(0.5f, em - mm, C2f);
                        float den1 = fmaf(0.5f, mp, C1f);
                        float den2 = fmaf(0.5f, ep - mp, C2f);
                        n[v] = num1 * num2;
                        d[v] = den1 * den2;
                    }
                    // n0/d0 + n1/d1 = (n0*d1 + n1*d0) * rcp(d0*d1); d > C1*C2 > 0
                    float num = n[0] * d[1] + n[1] * d[0];
                    float rden;
                    asm("rcp.approx.f32 %0, %1;" : "=f"(rden) : "f"(d[0] * d[1]));
                    tsum = fmaf(num, rden, tsum);
                }
            }
        }
        __syncthreads();   // protect buffer (g&1) before next prefetch reuses it
    }

    // ---- block reduction -> global double accumulator ----
    float s = tsum;
    #pragma unroll
    for (int off = 16; off; off >>= 1)
        s += __shfl_xor_sync(0xffffffffu, s, off);
    if ((tid & 31) == 0) sred[tid >> 5] = s;
    __syncthreads();
    if (tid == 0) {
        atomicAdd(&g_accum, (double)(sred[0] + sred[1]));
        __threadfence();
        unsigned prev = atomicAdd(&g_count, 1u);
        amLast = (prev == (unsigned)(NBLOCKS - 1));
    }
    __syncthreads();

    // ---- last block finalizes and resets state for the next graph replay ----
    if (amLast && tid == 0) {
        double total = atomicAdd(&g_accum, 0.0);   // coherent read
        out[0] = (float)(1.0 - total * (1.0 / (double)(NBATCH * IMG_H * IMG_W)));
        g_accum = 0.0;
        g_count = 0u;
    }
}

extern "C" void kernel_launch(void* const* d_in, const int* in_sizes, int n_in,
                              void* d_out, int out_size) {
    const float* pred = (const float*)d_in[0];
    const float* targ = (const float*)d_in[1];
    // d_in[2] (window) is a fixed Gaussian; weights are baked as immediates.
    (void)in_sizes; (void)n_in; (void)out_size;

    dim3 grid(IMG_W / TW, IMG_H / RH, NBATCH);   // 4 x 8 x 32 = 1024 blocks
    ssim_main<<<grid, THREADS>>>(pred, targ, (float*)d_out);
}

// round 16
// speedup vs baseline: 1.0782x; 1.0559x over previous
#include <cuda_runtime.h>
#include <cstdint>
#include <cstddef>

// ---------------------------------------------------------------------------
// SSIM loss, fused single kernel — 4-channel sum/difference formulation with
// DUAL-ACCUMULATOR aligned-only horizontal conv (R15 math, reshaped grid):
//   a = p+t, b = p-t;  conv(a), conv(b), conv(a^2), conv(b^2) suffice.
//   ACC1 += X[m] * rep(W[2m-1])        (m = 1..5)
//   ACC2 += X[m] * pack(W[2m-2],W[2m]) (m = 0..6, zero-padded ends)
//   h = add2(ACC1, rot32(ACC2))
// R16 delta: single-warp blocks (TW=64, 32 threads) -> 2048 blocks,
// 14 resident/SM => 0.988 waves: the 1.15-wave tail of the 1024-block shape
// (occ 14.7% vs 18.75% theoretical) disappears. Per-thread math unchanged.
// cp.async double-buffered streaming; 11-slot rolling f32x2 ring (4 ch),
// warp-uniform guarded scatter (proven structure).
// ---------------------------------------------------------------------------

#define IMG_H 512
#define IMG_W 512
#define NBATCH 32
#define THREADS 32
#define TW 64               // output cols per block
#define RH 64               // output rows per block
#define NIN (RH + 10)       // 74 input rows touched
#define RAWW 80             // staged row width in floats ([x0-8, x0+72))
#define NV4 (RAWW / 4)      // 20 float4 per row
#define GROUP 11
#define NGROUPS ((NIN + GROUP - 1) / GROUP)   // 7
#define NBLOCKS ((IMG_W / TW) * (IMG_H / RH) * NBATCH)   // 2048

using ull = unsigned long long;

__device__ double   g_accum = 0.0;
__device__ unsigned g_count = 0;

// ---- packed f32x2 helpers (sm_103a) ----
__device__ __forceinline__ ull pack2(float lo, float hi) {
    ull r; asm("mov.b64 %0, {%1, %2};" : "=l"(r) : "f"(lo), "f"(hi)); return r;
}
__device__ __forceinline__ ull fma2(ull a, ull b, ull c) {
    ull r; asm("fma.rn.f32x2 %0, %1, %2, %3;" : "=l"(r) : "l"(a), "l"(b), "l"(c)); return r;
}
__device__ __forceinline__ ull mul2(ull a, ull b) {
    ull r; asm("mul.rn.f32x2 %0, %1, %2;" : "=l"(r) : "l"(a), "l"(b)); return r;
}
__device__ __forceinline__ ull add2(ull a, ull b) {
    ull r; asm("add.rn.f32x2 %0, %1, %2;" : "=l"(r) : "l"(a), "l"(b)); return r;
}
__device__ __forceinline__ ull rot32(ull v) {           // swap 32-bit halves
    return (v << 32) | (v >> 32);
}
__device__ __forceinline__ float2 unpk2(ull v) {
    float2 f; asm("mov.b64 {%0, %1}, %2;" : "=f"(f.x), "=f"(f.y) : "l"(v)); return f;
}

__device__ __forceinline__ unsigned smem_u32(const void* p) {
    return (unsigned)__cvta_generic_to_shared(p);
}
__device__ __forceinline__ void cp_async16(unsigned saddr, const void* gaddr, int srcsize) {
    asm volatile("cp.async.ca.shared.global [%0], [%1], 16, %2;\n"
                 :: "r"(saddr), "l"(gaddr), "r"(srcsize));
}
__device__ __forceinline__ void cp_commit() { asm volatile("cp.async.commit_group;\n" ::: "memory"); }
__device__ __forceinline__ void cp_wait1()  { asm volatile("cp.async.wait_group 1;\n" ::: "memory"); }
__device__ __forceinline__ void cp_wait0()  { asm volatile("cp.async.wait_group 0;\n" ::: "memory"); }

// Issue cp.async for one 11-row group of both tensors into sbuf.
__device__ __forceinline__ void load_group(float* sbuf,  // [2][GROUP][RAWW]
                                           const float* __restrict__ P,
                                           const float* __restrict__ T,
                                           int g, int x0, int y0) {
    const int total = 2 * GROUP * NV4;  // 440
    for (int idx = threadIdx.x; idx < total; idx += THREADS) {
        int tsel = idx / (GROUP * NV4);
        int rem  = idx % (GROUP * NV4);
        int r    = rem / NV4;
        int cv   = rem % NV4;
        int i    = g * GROUP + r;
        int ir   = y0 - 5 + i;
        int c0   = x0 - 8 + cv * 4;
        bool ok = (i < NIN) && ((unsigned)ir < (unsigned)IMG_H) && ((unsigned)c0 < (unsigned)IMG_W);
        const float* src = tsel ? T : P;
        const float* gp  = ok ? (src + (size_t)ir * IMG_W + c0) : src;
        unsigned sa = smem_u32(sbuf + (tsel * GROUP + r) * RAWW + cv * 4);
        cp_async16(sa, gp, ok ? 16 : 0);
    }
}

__global__ void __launch_bounds__(THREADS)
ssim_main(const float* __restrict__ pred, const float* __restrict__ targ,
          float* __restrict__ out) {
    __shared__ __align__(16) float sraw[2][2][GROUP][RAWW];   // 13.75 KB

    const int x0 = blockIdx.x * TW;
    const int y0 = blockIdx.y * RH;
    const int b  = blockIdx.z;
    const float* P = pred + (size_t)b * (IMG_H * IMG_W);
    const float* T = targ + (size_t)b * (IMG_H * IMG_W);
    const int tid  = threadIdx.x;
    const int tid2 = 2 * tid;

    // 1D Gaussian weights (normalized) as compile-time literals.
    const float Wc[11] = {
        1.4867195e-06f, 1.3383023e-04f, 4.4318484e-03f, 5.3990967e-02f,
        2.4197073e-01f, 3.9894228e-01f, 2.4197073e-01f, 5.3990967e-02f,
        4.4318484e-03f, 1.3383023e-04f, 1.4867195e-06f };
    const float C1f = 1e-4f;   // 0.01^2
    const float C2f = 9e-4f;   // 0.03^2

    // Packed scatter weights (replicated), loop-invariant.
    ull W2[11];
    #pragma unroll
    for (int k = 0; k < 11; ++k) W2[k] = pack2(Wc[k], Wc[k]);
    const ull ONE2 = pack2(1.0f, 1.0f);
    const ull NEG2 = pack2(-1.0f, -1.0f);

    // Dual-accumulator hconv weights:
    // RW[m] = rep(W[2m-1]), m=1..5 ; PW[m] = (W[2m-2], W[2m]), m=0..6 (0-padded)
    ull RW[6], PW[7];
    #pragma unroll
    for (int m = 1; m <= 5; ++m) RW[m] = pack2(Wc[2 * m - 1], Wc[2 * m - 1]);
    PW[0] = pack2(0.0f, Wc[0]);
    #pragma unroll
    for (int m = 1; m <= 5; ++m) PW[m] = pack2(Wc[2 * m - 2], Wc[2 * m]);
    PW[6] = pack2(Wc[10], 0.0f);

    // Rolling vertical accumulators: 4 channels (a, b, a^2, b^2) x 11 slots.
    ull acc[4][GROUP];
    #pragma unroll
    for (int c = 0; c < 4; ++c)
        #pragma unroll
        for (int s = 0; s < GROUP; ++s) acc[c][s] = 0ull;

    float tsum = 0.f;

    // Prologue: prefetch group 0
    load_group(&sraw[0][0][0][0], P, T, 0, x0, y0);
    cp_commit();

    #pragma unroll 1
    for (int g = 0; g < NGROUPS; ++g) {
        if (g + 1 < NGROUPS) {
            load_group(&sraw[(g + 1) & 1][0][0][0], P, T, g + 1, x0, y0);
            cp_commit();
            cp_wait1();     // group g complete, group g+1 may be in flight
        } else {
            cp_wait0();
        }
        __syncwarp();

        const float* basep = &sraw[g & 1][0][0][0];
        const float* baset = &sraw[g & 1][1][0][0];

        #pragma unroll
        for (int j = 0; j < GROUP; ++j) {
            const int i = g * GROUP + j;
            if (i < NIN) {
                // ---- load aligned p/t pairs, form a = p+t, b = p-t ----
                ull Aa[7], Ab[7];
                #pragma unroll
                for (int m = 0; m < 7; ++m) {
                    ull Apm = *(const ull*)(basep + j * RAWW + tid2 + 2 + 2 * m);
                    ull Atm = *(const ull*)(baset + j * RAWW + tid2 + 2 + 2 * m);
                    Aa[m] = fma2(Atm, ONE2, Apm);   // p + t
                    Ab[m] = fma2(Atm, NEG2, Apm);   // p - t
                }

                // ---- dual-accumulator hconv over 4 channels ----
                ull A1a, A1b, A1sa, A1sb;   // ACC1 (m = 1..5)
                ull A2a, A2b, A2sa, A2sb;   // ACC2 (m = 0..6)
                {   // m = 0: ACC2 init
                    ull sa = mul2(Aa[0], Aa[0]);
                    ull sb = mul2(Ab[0], Ab[0]);
                    A2a  = mul2(Aa[0], PW[0]);
                    A2b  = mul2(Ab[0], PW[0]);
                    A2sa = mul2(sa,    PW[0]);
                    A2sb = mul2(sb,    PW[0]);
                }
                #pragma unroll
                for (int m = 1; m <= 5; ++m) {
                    ull sa = mul2(Aa[m], Aa[m]);
                    ull sb = mul2(Ab[m], Ab[m]);
                    if (m == 1) {
                        A1a  = mul2(Aa[m], RW[m]);
                        A1b  = mul2(Ab[m], RW[m]);
                        A1sa = mul2(sa,    RW[m]);
                        A1sb = mul2(sb,    RW[m]);
                    } else {
                        A1a  = fma2(Aa[m], RW[m], A1a);
                        A1b  = fma2(Ab[m], RW[m], A1b);
                        A1sa = fma2(sa,    RW[m], A1sa);
                        A1sb = fma2(sb,    RW[m], A1sb);
                    }
                    A2a  = fma2(Aa[m], PW[m], A2a);
                    A2b  = fma2(Ab[m], PW[m], A2b);
                    A2sa = fma2(sa,    PW[m], A2sa);
                    A2sb = fma2(sb,    PW[m], A2sb);
                }
                {   // m = 6: ACC2 tail
                    ull sa = mul2(Aa[6], Aa[6]);
                    ull sb = mul2(Ab[6], Ab[6]);
                    A2a  = fma2(Aa[6], PW[6], A2a);
                    A2b  = fma2(Ab[6], PW[6], A2b);
                    A2sa = fma2(sa,    PW[6], A2sa);
                    A2sb = fma2(sb,    PW[6], A2sb);
                }
                // combine: h = ACC1 + rot32(ACC2) -> (A1.lo+A2.hi, A1.hi+A2.lo)
                ull ha  = add2(A1a,  rot32(A2a));
                ull hb  = add2(A1b,  rot32(A2b));
                ull ha2 = add2(A1sa, rot32(A2sa));
                ull hb2 = add2(A1sb, rot32(A2sb));
                ull h[4] = { ha, hb, ha2, hb2 };

                // ---- vertical scatter into rolling ring (warp-uniform guards) ----
                #pragma unroll
                for (int k = 0; k < 11; ++k) {
                    const int s = (j - k + 11) % 11;     // compile-time
                    bool on = (i >= k) && (i - k < RH);
                    if (on) {
                        #pragma unroll
                        for (int ch = 0; ch < 4; ++ch) {
                            if (k == 0) acc[ch][s] = mul2(h[ch], W2[0]);   // fresh slot
                            else        acc[ch][s] = fma2(h[ch], W2[k], acc[ch][s]);
                        }
                    }
                }

                // ---- finalize output row oy = i - 10 ----
                if (i >= 10) {
                    const int f = (j + 1) % 11;          // compile-time
                    float2 mav = unpk2(acc[0][f]);   // mu_a = mu1+mu2
                    float2 mbv = unpk2(acc[1][f]);   // mu_b = mu1-mu2
                    float2 eav = unpk2(acc[2][f]);   // E[(p+t)^2]
                    float2 ebv = unpk2(acc[3][f]);   // E[(p-t)^2]
                    float n[2], d[2];
                    #pragma unroll
                    for (int v = 0; v < 2; ++v) {
                        float ma = v ? mav.y : mav.x;
                        float mb = v ? mbv.y : mbv.x;
                        float ea = v ? eav.y : eav.x;
                        float eb = v ? ebv.y : ebv.x;
                        float m2a = ma * ma;
                        float m2b = mb * mb;
                        float mp = m2a + m2b;   // 2(mu1^2 + mu2^2)
                        float mm = m2a - m2b;   // 4 mu1 mu2
                        float ep = ea + eb;     // 2(E[p^2] + E[t^2])
                        float em = ea - eb;     // 4 E[pt]
                        float num1 = fmaf(0.5f, mm, C1f);
                        float num2 = fmaf(0.5f, em - mm, C2f);
                        float den1 = fmaf(0.5f, mp, C1f);
                        float den2 = fmaf(0.5f, ep - mp, C2f);
                        n[v] = num1 * num2;
                        d[v] = den1 * den2;
                    }
                    // n0/d0 + n1/d1 = (n0*d1 + n1*d0) * rcp(d0*d1); d > C1*C2 > 0
                    float num = n[0] * d[1] + n[1] * d[0];
                    float rden;
                    asm("rcp.approx.f32 %0, %1;" : "=f"(rden) : "f"(d[0] * d[1]));
                    tsum = fmaf(num, rden, tsum);
                }
            }
        }
        __syncwarp();   // protect buffer (g&1) before next prefetch reuses it
    }

    // ---- warp reduction -> global double accumulator ----
    float s = tsum;
    #pragma unroll
    for (int off = 16; off; off >>= 1)
        s += __shfl_xor_sync(0xffffffffu, s, off);
    if (tid == 0) {
        atomicAdd(&g_accum, (double)s);
        __threadfence();
        unsigned prev = atomicAdd(&g_count, 1u);
        if (prev == (unsigned)(NBLOCKS - 1)) {
            // last block finalizes and resets state for the next graph replay
            double total = atomicAdd(&g_accum, 0.0);   // coherent read
            out[0] = (float)(1.0 - total * (1.0 / (double)(NBATCH * IMG_H * IMG_W)));
            g_accum = 0.0;
            g_count = 0u;
        }
    }
}

extern "C" void kernel_launch(void* const* d_in, const int* in_sizes, int n_in,
                              void* d_out, int out_size) {
    const float* pred = (const float*)d_in[0];
    const float* targ = (const float*)d_in[1];
    // d_in[2] (window) is a fixed Gaussian; weights are baked as immediates.
    (void)in_sizes; (void)n_in; (void)out_size;

    dim3 grid(IMG_W / TW, IMG_H / RH, NBATCH);   // 8 x 8 x 32 = 2048 blocks
    ssim_main<<<grid, THREADS>>>(pred, targ, (float*)d_out);
}